// round 1
// baseline (speedup 1.0000x reference)
#include <cuda_runtime.h>
#include <cstdint>
#include <math.h>

#define BB 2
#define SS 2048
#define HH 1024
#define NHH 16
#define HDD 64
#define MM (BB*SS)   // 4096

// ---------------- scratch (allocation-free: device globals) ----------------
__device__ float g_Q[BB*NHH*SS*HDD];
__device__ float g_K[BB*NHH*SS*HDD];
__device__ float g_V[BB*NHH*SS*HDD];
__device__ float g_AO[MM*HH];

// ---------------- projection GEMM: Y[m,o] = sum_h A[m,h] * W[o,h] ----------
// MODE 0: store into (b, nh, s, hd) layout.  MODE 1: store row-major [m*H+o].
template<int MODE>
__global__ void __launch_bounds__(256) gemm_proj(const float* __restrict__ A,
                                                 const float* __restrict__ W,
                                                 float* __restrict__ Y)
{
    __shared__ float As[64*17];
    __shared__ float Ws[64*17];

    const int tid = threadIdx.x;
    const int tx = tid & 15, ty = tid >> 4;
    const int m0 = blockIdx.y * 64;
    const int n0 = blockIdx.x * 64;
    const int r0 = ty * 4, c0 = tx * 4;

    const int lrow = tid >> 2;      // 0..63
    const int lkg  = (tid & 3) * 4; // 0,4,8,12

    float acc[4][4];
    #pragma unroll
    for (int i = 0; i < 4; i++)
        #pragma unroll
        for (int j = 0; j < 4; j++) acc[i][j] = 0.f;

    for (int ko = 0; ko < HH; ko += 16) {
        __syncthreads();
        {
            float4 av = *(const float4*)&A[(m0 + lrow) * HH + ko + lkg];
            As[lrow*17 + lkg + 0] = av.x;
            As[lrow*17 + lkg + 1] = av.y;
            As[lrow*17 + lkg + 2] = av.z;
            As[lrow*17 + lkg + 3] = av.w;
            float4 wv = *(const float4*)&W[(n0 + lrow) * HH + ko + lkg];
            Ws[lrow*17 + lkg + 0] = wv.x;
            Ws[lrow*17 + lkg + 1] = wv.y;
            Ws[lrow*17 + lkg + 2] = wv.z;
            Ws[lrow*17 + lkg + 3] = wv.w;
        }
        __syncthreads();

        #pragma unroll
        for (int k = 0; k < 16; k++) {
            float a[4], bq[4];
            #pragma unroll
            for (int i = 0; i < 4; i++) a[i] = As[(r0 + i)*17 + k];
            #pragma unroll
            for (int j = 0; j < 4; j++) bq[j] = Ws[(c0 + j)*17 + k];
            #pragma unroll
            for (int i = 0; i < 4; i++)
                #pragma unroll
                for (int j = 0; j < 4; j++)
                    acc[i][j] = fmaf(a[i], bq[j], acc[i][j]);
        }
    }

    #pragma unroll
    for (int i = 0; i < 4; i++) {
        const int m = m0 + r0 + i;
        #pragma unroll
        for (int j = 0; j < 4; j++) {
            const int o = n0 + c0 + j;
            if (MODE == 0) {
                const int b  = m >> 11;     // /S
                const int s  = m & (SS-1);
                const int nh = o >> 6;      // /HD
                const int hd = o & 63;
                Y[((b*NHH + nh)*SS + s)*HDD + hd] = acc[i][j];
            } else {
                Y[m*HH + o] = acc[i][j];
            }
        }
    }
}

// ---------------- RoPE (in-place on Q and K, bhsd layout) -------------------
__global__ void __launch_bounds__(256) rope_kernel(float* __restrict__ Q,
                                                   float* __restrict__ K,
                                                   const int* __restrict__ pos_ids)
{
    int idx = blockIdx.x * blockDim.x + threadIdx.x;   // B*NH*S*32 = 2,097,152
    if (idx >= BB*NHH*SS*(HDD/2)) return;
    const int i  = idx & 31;
    const int s  = (idx >> 5) & (SS - 1);
    const int bh = idx >> 16;
    const int b  = bh >> 4;

    int p = pos_ids[b*SS + s];
    p = min(max(p, 0), SS - 1);

    const float inv = expf(-(float)(2*i) / (float)HDD * logf(10000.0f));
    const float ang = (float)p * inv;
    float sn, cs;
    sincosf(ang, &sn, &cs);

    const int base = (bh*SS + s)*HDD;
    float q0 = Q[base + i], q1 = Q[base + i + 32];
    Q[base + i]      = q0*cs - q1*sn;
    Q[base + i + 32] = q1*cs + q0*sn;
    float k0 = K[base + i], k1 = K[base + i + 32];
    K[base + i]      = k0*cs - k1*sn;
    K[base + i + 32] = k1*cs + k0*sn;
}

// ---------------- flash attention (causal, fp32, online softmax) ------------
// grid: (S/64, B*NH); block 256 (16x16 threads, 4x4 micro-tiles)
__global__ void __launch_bounds__(256) flash_kernel(const float* __restrict__ Q,
                                                    const float* __restrict__ K,
                                                    const float* __restrict__ V,
                                                    float* __restrict__ AO)
{
    extern __shared__ float sm[];
    float* Qs = sm;                    // 64*64
    float* Ks = Qs + 64*64;            // 64*65 (padded)
    float* Vs = Ks + 64*65;            // 64*65 (padded)
    float* Ps = Vs + 64*65;            // 64*64

    const int tid = threadIdx.x;
    const int tx = tid & 15, ty = tid >> 4;
    const int r0 = ty * 4, c0 = tx * 4;
    const int bh = blockIdx.y;
    const int qt = blockIdx.x;
    const int q0 = qt * 64;
    const int base = bh * SS * HDD;

    // load Q tile
    for (int t = tid; t < 64*16; t += 256) {
        const int r = t >> 4, c4 = (t & 15) * 4;
        float4 v = *(const float4*)&Q[base + (q0 + r)*HDD + c4];
        *(float4*)&Qs[r*64 + c4] = v;
    }

    float m_i[4], l_i[4], acc[4][4];
    #pragma unroll
    for (int i = 0; i < 4; i++) {
        m_i[i] = -1e30f; l_i[i] = 0.f;
        #pragma unroll
        for (int j = 0; j < 4; j++) acc[i][j] = 0.f;
    }

    for (int kt = 0; kt <= qt; kt++) {
        const int k0 = kt * 64;
        __syncthreads();
        for (int t = tid; t < 64*16; t += 256) {
            const int r = t >> 4, c4 = (t & 15) * 4;
            float4 kv = *(const float4*)&K[base + (k0 + r)*HDD + c4];
            Ks[r*65 + c4 + 0] = kv.x; Ks[r*65 + c4 + 1] = kv.y;
            Ks[r*65 + c4 + 2] = kv.z; Ks[r*65 + c4 + 3] = kv.w;
            float4 vv = *(const float4*)&V[base + (k0 + r)*HDD + c4];
            Vs[r*65 + c4 + 0] = vv.x; Vs[r*65 + c4 + 1] = vv.y;
            Vs[r*65 + c4 + 2] = vv.z; Vs[r*65 + c4 + 3] = vv.w;
        }
        __syncthreads();

        // GEMM1: scores = Q . K^T
        float sc[4][4];
        #pragma unroll
        for (int i = 0; i < 4; i++)
            #pragma unroll
            for (int j = 0; j < 4; j++) sc[i][j] = 0.f;

        #pragma unroll 16
        for (int d = 0; d < 64; d++) {
            float a[4], bq[4];
            #pragma unroll
            for (int i = 0; i < 4; i++) a[i] = Qs[(r0 + i)*64 + d];
            #pragma unroll
            for (int j = 0; j < 4; j++) bq[j] = Ks[(c0 + j)*65 + d];
            #pragma unroll
            for (int i = 0; i < 4; i++)
                #pragma unroll
                for (int j = 0; j < 4; j++)
                    sc[i][j] = fmaf(a[i], bq[j], sc[i][j]);
        }

        // scale + causal mask + online softmax
        #pragma unroll
        for (int i = 0; i < 4; i++) {
            #pragma unroll
            for (int j = 0; j < 4; j++) {
                float v = sc[i][j] * 0.125f;   // 1/sqrt(64)
                if (k0 + c0 + j > q0 + r0 + i) v = -1e30f;
                sc[i][j] = v;
            }
            float mx = fmaxf(fmaxf(sc[i][0], sc[i][1]), fmaxf(sc[i][2], sc[i][3]));
            #pragma unroll
            for (int off = 1; off < 16; off <<= 1)
                mx = fmaxf(mx, __shfl_xor_sync(0xffffffffu, mx, off));
            const float mnew = fmaxf(m_i[i], mx);
            float p[4], lsum = 0.f;
            #pragma unroll
            for (int j = 0; j < 4; j++) {
                p[j] = expf(sc[i][j] - mnew);
                lsum += p[j];
            }
            #pragma unroll
            for (int off = 1; off < 16; off <<= 1)
                lsum += __shfl_xor_sync(0xffffffffu, lsum, off);
            const float alpha = expf(m_i[i] - mnew);
            l_i[i] = l_i[i]*alpha + lsum;
            m_i[i] = mnew;
            #pragma unroll
            for (int j = 0; j < 4; j++) {
                acc[i][j] *= alpha;
                Ps[(r0 + i)*64 + c0 + j] = p[j];
            }
        }
        __syncthreads();

        // GEMM2: O += P . V
        #pragma unroll 16
        for (int c = 0; c < 64; c++) {
            float p[4], vv[4];
            #pragma unroll
            for (int i = 0; i < 4; i++) p[i] = Ps[(r0 + i)*64 + c];
            #pragma unroll
            for (int j = 0; j < 4; j++) vv[j] = Vs[c*65 + c0 + j];
            #pragma unroll
            for (int i = 0; i < 4; i++)
                #pragma unroll
                for (int j = 0; j < 4; j++)
                    acc[i][j] = fmaf(p[i], vv[j], acc[i][j]);
        }
    }

    // epilogue: normalize and store to (b, s, h) layout
    const int b = bh >> 4, nh = bh & 15;
    #pragma unroll
    for (int i = 0; i < 4; i++) {
        const float inv_l = 1.f / l_i[i];
        const int srow = q0 + r0 + i;
        #pragma unroll
        for (int j = 0; j < 4; j++)
            AO[(b*SS + srow)*HH + nh*HDD + c0 + j] = acc[i][j] * inv_l;
    }
}

// ---------------- launcher ---------------------------------------------------
static const int FLASH_SMEM = (64*64 + 64*65 + 64*65 + 64*64) * (int)sizeof(float); // 66048

extern "C" void kernel_launch(void* const* d_in, const int* in_sizes, int n_in,
                              void* d_out, int out_size)
{
    (void)in_sizes; (void)n_in; (void)out_size;
    const float* hs = (const float*)d_in[0];
    // d_in[1] = attention_mask: exactly causal (tril 0 / finfo.min) -> implemented directly
    const float* wq = (const float*)d_in[2];
    const float* wk = (const float*)d_in[3];
    const float* wv = (const float*)d_in[4];
    const float* wo = (const float*)d_in[5];
    const int*  pos = (const int*)d_in[6];
    float* out = (float*)d_out;

    float *Q, *K, *V, *AO;
    cudaGetSymbolAddress((void**)&Q,  g_Q);
    cudaGetSymbolAddress((void**)&K,  g_K);
    cudaGetSymbolAddress((void**)&V,  g_V);
    cudaGetSymbolAddress((void**)&AO, g_AO);

    static bool attr_done = false;
    if (!attr_done) {
        cudaFuncSetAttribute(flash_kernel,
                             cudaFuncAttributeMaxDynamicSharedMemorySize, FLASH_SMEM);
        attr_done = true;
    }

    const dim3 gemm_grid(HH/64, MM/64);   // (16, 64)
    gemm_proj<0><<<gemm_grid, 256>>>(hs, wq, Q);
    gemm_proj<0><<<gemm_grid, 256>>>(hs, wk, K);
    gemm_proj<0><<<gemm_grid, 256>>>(hs, wv, V);

    rope_kernel<<<(BB*NHH*SS*(HDD/2)) / 256, 256>>>(Q, K, pos);

    flash_kernel<<<dim3(SS/64, BB*NHH), 256, FLASH_SMEM>>>(Q, K, V, AO);

    gemm_proj<1><<<gemm_grid, 256>>>(AO, wo, out);
}

// round 2
// speedup vs baseline: 1.7943x; 1.7943x over previous
#include <cuda_runtime.h>
#include <cstdint>
#include <math.h>

#define BB 2
#define SS 2048
#define HH 1024
#define NHH 16
#define HDD 64
#define MM (BB*SS)   // 4096

// ---------------- scratch (allocation-free: device globals) ----------------
__device__ float g_Q[BB*NHH*SS*HDD];
__device__ float g_K[BB*NHH*SS*HDD];
__device__ float g_V[BB*NHH*SS*HDD];
__device__ float g_AO[MM*HH];

// ---------------- tf32 helpers ---------------------------------------------
__device__ __forceinline__ uint32_t f2tf32(float f) {
    uint32_t u;
    asm("cvt.rna.tf32.f32 %0, %1;" : "=r"(u) : "f"(f));
    return u;
}

__device__ __forceinline__ void mma_tf32(float c[4], const uint32_t a[4], const uint32_t b[2]) {
    asm volatile(
        "mma.sync.aligned.m16n8k8.row.col.f32.tf32.tf32.f32 "
        "{%0,%1,%2,%3}, {%4,%5,%6,%7}, {%8,%9}, {%0,%1,%2,%3};"
        : "+f"(c[0]), "+f"(c[1]), "+f"(c[2]), "+f"(c[3])
        : "r"(a[0]), "r"(a[1]), "r"(a[2]), "r"(a[3]),
          "r"(b[0]), "r"(b[1]));
}

// ---------------- tf32 tensor-core projection GEMM --------------------------
// Y[m,o] = sum_h A[m,h] * W[o,h]   (A: MxK row-major, W: NxK row-major)
// Block tile 128(M) x 128(N) x 32(K). 256 threads = 8 warps as 4(m) x 2(n).
// Warp tile 32x64: 2(mi) x 8(ni) m16n8k8 MMAs per k8-step.
// Smem XOR swizzle: phys_col = col ^ ((row & 7) << 2)  -> conflict-free
// fragment LDS and aligned 16B STS.
// MODE 0: scatter to (b, nh, s, hd).  MODE 1: row-major [m*HH + o].
template<int MODE>
__global__ void __launch_bounds__(256) gemm_tf32(const float* __restrict__ A,
                                                 const float* __restrict__ W,
                                                 float* __restrict__ Y)
{
    extern __shared__ uint32_t smem[];          // 2 stages x (As 4096 + Ws 4096)
    const int tid  = threadIdx.x;
    const int w    = tid >> 5;
    const int lane = tid & 31;
    const int g    = lane >> 2;                 // 0..7
    const int tg   = lane & 3;                  // 0..3
    const int wm   = (w & 3) * 32;
    const int wn   = (w >> 2) * 64;
    const int m0   = blockIdx.y * 128;
    const int n0   = blockIdx.x * 128;

    float acc[2][8][4];
    #pragma unroll
    for (int mi = 0; mi < 2; mi++)
        #pragma unroll
        for (int ni = 0; ni < 8; ni++)
            #pragma unroll
            for (int r = 0; r < 4; r++) acc[mi][ni][r] = 0.f;

    float4 a_st[4], b_st[4];

    // per-thread staging map: idx = r*256 + tid -> (row = idx>>3, chunk j = idx&7)
    #define LDG_TILE(KO)                                                         \
        _Pragma("unroll")                                                        \
        for (int r = 0; r < 4; r++) {                                            \
            const int idx = r * 256 + tid;                                       \
            const int row = idx >> 3;                                            \
            const int j   = idx & 7;                                             \
            a_st[r] = *(const float4*)&A[(size_t)(m0 + row) * HH + (KO) + j*4];  \
            b_st[r] = *(const float4*)&W[(size_t)(n0 + row) * HH + (KO) + j*4];  \
        }

    #define STS_TILE(STAGE)                                                      \
        {                                                                        \
            uint32_t* dA = smem + (STAGE) * 8192;                                \
            uint32_t* dW = dA + 4096;                                            \
            _Pragma("unroll")                                                    \
            for (int r = 0; r < 4; r++) {                                        \
                const int idx = r * 256 + tid;                                   \
                const int row = idx >> 3;                                        \
                const int j   = idx & 7;                                         \
                const int jp  = j ^ (row & 7);                                   \
                uint4 av = make_uint4(f2tf32(a_st[r].x), f2tf32(a_st[r].y),      \
                                      f2tf32(a_st[r].z), f2tf32(a_st[r].w));     \
                *(uint4*)&dA[row * 32 + jp * 4] = av;                            \
                uint4 wv = make_uint4(f2tf32(b_st[r].x), f2tf32(b_st[r].y),      \
                                      f2tf32(b_st[r].z), f2tf32(b_st[r].w));     \
                *(uint4*)&dW[row * 32 + jp * 4] = wv;                            \
            }                                                                    \
        }

    LDG_TILE(0);
    STS_TILE(0);
    __syncthreads();

    const int NITER = HH / 32;                  // 32
    for (int it = 0; it < NITER; it++) {
        if (it + 1 < NITER) LDG_TILE((it + 1) * 32);

        const uint32_t* cA = smem + (it & 1) * 8192;
        const uint32_t* cW = cA + 4096;

        #pragma unroll
        for (int kk = 0; kk < 4; kk++) {
            const int kc = kk * 8;
            const int s1 = (kc + tg)     ^ (g << 2);
            const int s2 = (kc + tg + 4) ^ (g << 2);

            uint32_t a[2][4], b[8][2];
            #pragma unroll
            for (int mi = 0; mi < 2; mi++) {
                const int r0 = (wm + mi * 16 + g) * 32;
                const int r8 = r0 + 8 * 32;
                a[mi][0] = cA[r0 + s1];
                a[mi][1] = cA[r8 + s1];
                a[mi][2] = cA[r0 + s2];
                a[mi][3] = cA[r8 + s2];
            }
            #pragma unroll
            for (int ni = 0; ni < 8; ni++) {
                const int nr = (wn + ni * 8 + g) * 32;
                b[ni][0] = cW[nr + s1];
                b[ni][1] = cW[nr + s2];
            }
            #pragma unroll
            for (int mi = 0; mi < 2; mi++)
                #pragma unroll
                for (int ni = 0; ni < 8; ni++)
                    mma_tf32(acc[mi][ni], a[mi], b[ni]);
        }

        if (it + 1 < NITER) STS_TILE((it + 1) & 1);
        __syncthreads();
    }

    // epilogue: c0,c1 at (row, 2tg), c2,c3 at (row+8, 2tg) -> float2 stores
    #pragma unroll
    for (int mi = 0; mi < 2; mi++) {
        #pragma unroll
        for (int ni = 0; ni < 8; ni++) {
            const int row = m0 + wm + mi * 16 + g;
            const int col = n0 + wn + ni * 8 + 2 * tg;
            float2 v0 = make_float2(acc[mi][ni][0], acc[mi][ni][1]);
            float2 v1 = make_float2(acc[mi][ni][2], acc[mi][ni][3]);
            if (MODE == 0) {
                const int nh = col >> 6, hd = col & 63;
                {
                    const int b_ = row >> 11, s = row & (SS - 1);
                    *(float2*)&Y[(((size_t)(b_ * NHH + nh) * SS + s) * HDD) + hd] = v0;
                }
                {
                    const int row8 = row + 8;
                    const int b_ = row8 >> 11, s = row8 & (SS - 1);
                    *(float2*)&Y[(((size_t)(b_ * NHH + nh) * SS + s) * HDD) + hd] = v1;
                }
            } else {
                *(float2*)&Y[(size_t)row * HH + col] = v0;
                *(float2*)&Y[(size_t)(row + 8) * HH + col] = v1;
            }
        }
    }
    #undef LDG_TILE
    #undef STS_TILE
}

// ---------------- RoPE (in-place on Q and K, bhsd layout) -------------------
__global__ void __launch_bounds__(256) rope_kernel(float* __restrict__ Q,
                                                   float* __restrict__ K,
                                                   const int* __restrict__ pos_ids)
{
    int idx = blockIdx.x * blockDim.x + threadIdx.x;
    if (idx >= BB*NHH*SS*(HDD/2)) return;
    const int i  = idx & 31;
    const int s  = (idx >> 5) & (SS - 1);
    const int bh = idx >> 16;
    const int b  = bh >> 4;

    int p = pos_ids[b*SS + s];
    p = min(max(p, 0), SS - 1);

    const float inv = expf(-(float)(2*i) / (float)HDD * logf(10000.0f));
    const float ang = (float)p * inv;
    float sn, cs;
    sincosf(ang, &sn, &cs);

    const int base = (bh*SS + s)*HDD;
    float q0 = Q[base + i], q1 = Q[base + i + 32];
    Q[base + i]      = q0*cs - q1*sn;
    Q[base + i + 32] = q1*cs + q0*sn;
    float k0 = K[base + i], k1 = K[base + i + 32];
    K[base + i]      = k0*cs - k1*sn;
    K[base + i + 32] = k1*cs + k0*sn;
}

// ---------------- flash attention (causal, fp32, online softmax) ------------
__global__ void __launch_bounds__(256) flash_kernel(const float* __restrict__ Q,
                                                    const float* __restrict__ K,
                                                    const float* __restrict__ V,
                                                    float* __restrict__ AO)
{
    extern __shared__ float sm[];
    float* Qs = sm;                    // 64*64
    float* Ks = Qs + 64*64;            // 64*65 (padded)
    float* Vs = Ks + 64*65;            // 64*65 (padded)
    float* Ps = Vs + 64*65;            // 64*64

    const int tid = threadIdx.x;
    const int tx = tid & 15, ty = tid >> 4;
    const int r0 = ty * 4, c0 = tx * 4;
    const int bh = blockIdx.y;
    const int qt = blockIdx.x;
    const int q0 = qt * 64;
    const int base = bh * SS * HDD;

    for (int t = tid; t < 64*16; t += 256) {
        const int r = t >> 4, c4 = (t & 15) * 4;
        float4 v = *(const float4*)&Q[base + (q0 + r)*HDD + c4];
        *(float4*)&Qs[r*64 + c4] = v;
    }

    float m_i[4], l_i[4], acc[4][4];
    #pragma unroll
    for (int i = 0; i < 4; i++) {
        m_i[i] = -1e30f; l_i[i] = 0.f;
        #pragma unroll
        for (int j = 0; j < 4; j++) acc[i][j] = 0.f;
    }

    for (int kt = 0; kt <= qt; kt++) {
        const int k0 = kt * 64;
        __syncthreads();
        for (int t = tid; t < 64*16; t += 256) {
            const int r = t >> 4, c4 = (t & 15) * 4;
            float4 kv = *(const float4*)&K[base + (k0 + r)*HDD + c4];
            Ks[r*65 + c4 + 0] = kv.x; Ks[r*65 + c4 + 1] = kv.y;
            Ks[r*65 + c4 + 2] = kv.z; Ks[r*65 + c4 + 3] = kv.w;
            float4 vv = *(const float4*)&V[base + (k0 + r)*HDD + c4];
            Vs[r*65 + c4 + 0] = vv.x; Vs[r*65 + c4 + 1] = vv.y;
            Vs[r*65 + c4 + 2] = vv.z; Vs[r*65 + c4 + 3] = vv.w;
        }
        __syncthreads();

        float sc[4][4];
        #pragma unroll
        for (int i = 0; i < 4; i++)
            #pragma unroll
            for (int j = 0; j < 4; j++) sc[i][j] = 0.f;

        #pragma unroll 16
        for (int d = 0; d < 64; d++) {
            float a[4], bq[4];
            #pragma unroll
            for (int i = 0; i < 4; i++) a[i] = Qs[(r0 + i)*64 + d];
            #pragma unroll
            for (int j = 0; j < 4; j++) bq[j] = Ks[(c0 + j)*65 + d];
            #pragma unroll
            for (int i = 0; i < 4; i++)
                #pragma unroll
                for (int j = 0; j < 4; j++)
                    sc[i][j] = fmaf(a[i], bq[j], sc[i][j]);
        }

        #pragma unroll
        for (int i = 0; i < 4; i++) {
            #pragma unroll
            for (int j = 0; j < 4; j++) {
                float v = sc[i][j] * 0.125f;
                if (k0 + c0 + j > q0 + r0 + i) v = -1e30f;
                sc[i][j] = v;
            }
            float mx = fmaxf(fmaxf(sc[i][0], sc[i][1]), fmaxf(sc[i][2], sc[i][3]));
            #pragma unroll
            for (int off = 1; off < 16; off <<= 1)
                mx = fmaxf(mx, __shfl_xor_sync(0xffffffffu, mx, off));
            const float mnew = fmaxf(m_i[i], mx);
            float p[4], lsum = 0.f;
            #pragma unroll
            for (int j = 0; j < 4; j++) {
                p[j] = expf(sc[i][j] - mnew);
                lsum += p[j];
            }
            #pragma unroll
            for (int off = 1; off < 16; off <<= 1)
                lsum += __shfl_xor_sync(0xffffffffu, lsum, off);
            const float alpha = expf(m_i[i] - mnew);
            l_i[i] = l_i[i]*alpha + lsum;
            m_i[i] = mnew;
            #pragma unroll
            for (int j = 0; j < 4; j++) {
                acc[i][j] *= alpha;
                Ps[(r0 + i)*64 + c0 + j] = p[j];
            }
        }
        __syncthreads();

        #pragma unroll 16
        for (int c = 0; c < 64; c++) {
            float p[4], vv[4];
            #pragma unroll
            for (int i = 0; i < 4; i++) p[i] = Ps[(r0 + i)*64 + c];
            #pragma unroll
            for (int j = 0; j < 4; j++) vv[j] = Vs[c*65 + c0 + j];
            #pragma unroll
            for (int i = 0; i < 4; i++)
                #pragma unroll
                for (int j = 0; j < 4; j++)
                    acc[i][j] = fmaf(p[i], vv[j], acc[i][j]);
        }
    }

    const int b = bh >> 4, nh = bh & 15;
    #pragma unroll
    for (int i = 0; i < 4; i++) {
        const float inv_l = 1.f / l_i[i];
        const int srow = q0 + r0 + i;
        #pragma unroll
        for (int j = 0; j < 4; j++)
            AO[(b*SS + srow)*HH + nh*HDD + c0 + j] = acc[i][j] * inv_l;
    }
}

// ---------------- launcher ---------------------------------------------------
static const int FLASH_SMEM = (64*64 + 64*65 + 64*65 + 64*64) * (int)sizeof(float); // 66048
static const int GEMM_SMEM  = 2 * 8192 * (int)sizeof(uint32_t);                     // 65536

extern "C" void kernel_launch(void* const* d_in, const int* in_sizes, int n_in,
                              void* d_out, int out_size)
{
    (void)in_sizes; (void)n_in; (void)out_size;
    const float* hs = (const float*)d_in[0];
    // d_in[1] = attention_mask: exactly causal -> implemented directly
    const float* wq = (const float*)d_in[2];
    const float* wk = (const float*)d_in[3];
    const float* wv = (const float*)d_in[4];
    const float* wo = (const float*)d_in[5];
    const int*  pos = (const int*)d_in[6];
    float* out = (float*)d_out;

    float *Q, *K, *V, *AO;
    cudaGetSymbolAddress((void**)&Q,  g_Q);
    cudaGetSymbolAddress((void**)&K,  g_K);
    cudaGetSymbolAddress((void**)&V,  g_V);
    cudaGetSymbolAddress((void**)&AO, g_AO);

    static bool attr_done = false;
    if (!attr_done) {
        cudaFuncSetAttribute(flash_kernel,
                             cudaFuncAttributeMaxDynamicSharedMemorySize, FLASH_SMEM);
        cudaFuncSetAttribute(gemm_tf32<0>,
                             cudaFuncAttributeMaxDynamicSharedMemorySize, GEMM_SMEM);
        cudaFuncSetAttribute(gemm_tf32<1>,
                             cudaFuncAttributeMaxDynamicSharedMemorySize, GEMM_SMEM);
        attr_done = true;
    }

    const dim3 gemm_grid(HH/128, MM/128);   // (8, 32)
    gemm_tf32<0><<<gemm_grid, 256, GEMM_SMEM>>>(hs, wq, Q);
    gemm_tf32<0><<<gemm_grid, 256, GEMM_SMEM>>>(hs, wk, K);
    gemm_tf32<0><<<gemm_grid, 256, GEMM_SMEM>>>(hs, wv, V);

    rope_kernel<<<(BB*NHH*SS*(HDD/2)) / 256, 256>>>(Q, K, pos);

    flash_kernel<<<dim3(SS/64, BB*NHH), 256, FLASH_SMEM>>>(Q, K, V, AO);

    gemm_tf32<1><<<gemm_grid, 256, GEMM_SMEM>>>(AO, wo, out);
}

// round 3
// speedup vs baseline: 3.2894x; 1.8332x over previous
#include <cuda_runtime.h>
#include <cstdint>
#include <math.h>

#define BB 2
#define SS 2048
#define HH 1024
#define NHH 16
#define HDD 64
#define MM (BB*SS)   // 4096

// ---------------- scratch (allocation-free: device globals) ----------------
__device__ float g_Q[BB*NHH*SS*HDD];
__device__ float g_K[BB*NHH*SS*HDD];
__device__ float g_V[BB*NHH*SS*HDD];
__device__ float g_AO[MM*HH];

// ---------------- tf32 helpers ---------------------------------------------
__device__ __forceinline__ uint32_t f2tf32(float f) {
    uint32_t u;
    asm("cvt.rna.tf32.f32 %0, %1;" : "=r"(u) : "f"(f));
    return u;
}

__device__ __forceinline__ void mma_tf32(float c[4], const uint32_t a[4], const uint32_t b[2]) {
    asm volatile(
        "mma.sync.aligned.m16n8k8.row.col.f32.tf32.tf32.f32 "
        "{%0,%1,%2,%3}, {%4,%5,%6,%7}, {%8,%9}, {%0,%1,%2,%3};"
        : "+f"(c[0]), "+f"(c[1]), "+f"(c[2]), "+f"(c[3])
        : "r"(a[0]), "r"(a[1]), "r"(a[2]), "r"(a[3]),
          "r"(b[0]), "r"(b[1]));
}

// ---------------- tf32 tensor-core projection GEMM --------------------------
// (unchanged from R2 — 128x128x32 tile, XOR swizzle, double-buffered)
template<int MODE>
__global__ void __launch_bounds__(256) gemm_tf32(const float* __restrict__ A,
                                                 const float* __restrict__ W,
                                                 float* __restrict__ Y)
{
    extern __shared__ uint32_t smem[];
    const int tid  = threadIdx.x;
    const int w    = tid >> 5;
    const int lane = tid & 31;
    const int g    = lane >> 2;
    const int tg   = lane & 3;
    const int wm   = (w & 3) * 32;
    const int wn   = (w >> 2) * 64;
    const int m0   = blockIdx.y * 128;
    const int n0   = blockIdx.x * 128;

    float acc[2][8][4];
    #pragma unroll
    for (int mi = 0; mi < 2; mi++)
        #pragma unroll
        for (int ni = 0; ni < 8; ni++)
            #pragma unroll
            for (int r = 0; r < 4; r++) acc[mi][ni][r] = 0.f;

    float4 a_st[4], b_st[4];

    #define LDG_TILE(KO)                                                         \
        _Pragma("unroll")                                                        \
        for (int r = 0; r < 4; r++) {                                            \
            const int idx = r * 256 + tid;                                       \
            const int row = idx >> 3;                                            \
            const int j   = idx & 7;                                             \
            a_st[r] = *(const float4*)&A[(size_t)(m0 + row) * HH + (KO) + j*4];  \
            b_st[r] = *(const float4*)&W[(size_t)(n0 + row) * HH + (KO) + j*4];  \
        }

    #define STS_TILE(STAGE)                                                      \
        {                                                                        \
            uint32_t* dA = smem + (STAGE) * 8192;                                \
            uint32_t* dW = dA + 4096;                                            \
            _Pragma("unroll")                                                    \
            for (int r = 0; r < 4; r++) {                                        \
                const int idx = r * 256 + tid;                                   \
                const int row = idx >> 3;                                        \
                const int j   = idx & 7;                                         \
                const int jp  = j ^ (row & 7);                                   \
                uint4 av = make_uint4(f2tf32(a_st[r].x), f2tf32(a_st[r].y),      \
                                      f2tf32(a_st[r].z), f2tf32(a_st[r].w));     \
                *(uint4*)&dA[row * 32 + jp * 4] = av;                            \
                uint4 wv = make_uint4(f2tf32(b_st[r].x), f2tf32(b_st[r].y),      \
                                      f2tf32(b_st[r].z), f2tf32(b_st[r].w));     \
                *(uint4*)&dW[row * 32 + jp * 4] = wv;                            \
            }                                                                    \
        }

    LDG_TILE(0);
    STS_TILE(0);
    __syncthreads();

    const int NITER = HH / 32;
    for (int it = 0; it < NITER; it++) {
        if (it + 1 < NITER) LDG_TILE((it + 1) * 32);

        const uint32_t* cA = smem + (it & 1) * 8192;
        const uint32_t* cW = cA + 4096;

        #pragma unroll
        for (int kk = 0; kk < 4; kk++) {
            const int kc = kk * 8;
            const int s1 = (kc + tg)     ^ (g << 2);
            const int s2 = (kc + tg + 4) ^ (g << 2);

            uint32_t a[2][4], b[8][2];
            #pragma unroll
            for (int mi = 0; mi < 2; mi++) {
                const int r0 = (wm + mi * 16 + g) * 32;
                const int r8 = r0 + 8 * 32;
                a[mi][0] = cA[r0 + s1];
                a[mi][1] = cA[r8 + s1];
                a[mi][2] = cA[r0 + s2];
                a[mi][3] = cA[r8 + s2];
            }
            #pragma unroll
            for (int ni = 0; ni < 8; ni++) {
                const int nr = (wn + ni * 8 + g) * 32;
                b[ni][0] = cW[nr + s1];
                b[ni][1] = cW[nr + s2];
            }
            #pragma unroll
            for (int mi = 0; mi < 2; mi++)
                #pragma unroll
                for (int ni = 0; ni < 8; ni++)
                    mma_tf32(acc[mi][ni], a[mi], b[ni]);
        }

        if (it + 1 < NITER) STS_TILE((it + 1) & 1);
        __syncthreads();
    }

    #pragma unroll
    for (int mi = 0; mi < 2; mi++) {
        #pragma unroll
        for (int ni = 0; ni < 8; ni++) {
            const int row = m0 + wm + mi * 16 + g;
            const int col = n0 + wn + ni * 8 + 2 * tg;
            float2 v0 = make_float2(acc[mi][ni][0], acc[mi][ni][1]);
            float2 v1 = make_float2(acc[mi][ni][2], acc[mi][ni][3]);
            if (MODE == 0) {
                const int nh = col >> 6, hd = col & 63;
                {
                    const int b_ = row >> 11, s = row & (SS - 1);
                    *(float2*)&Y[(((size_t)(b_ * NHH + nh) * SS + s) * HDD) + hd] = v0;
                }
                {
                    const int row8 = row + 8;
                    const int b_ = row8 >> 11, s = row8 & (SS - 1);
                    *(float2*)&Y[(((size_t)(b_ * NHH + nh) * SS + s) * HDD) + hd] = v1;
                }
            } else {
                *(float2*)&Y[(size_t)row * HH + col] = v0;
                *(float2*)&Y[(size_t)(row + 8) * HH + col] = v1;
            }
        }
    }
    #undef LDG_TILE
    #undef STS_TILE
}

// ---------------- RoPE (in-place on Q and K, bhsd layout) -------------------
__global__ void __launch_bounds__(256) rope_kernel(float* __restrict__ Q,
                                                   float* __restrict__ K,
                                                   const int* __restrict__ pos_ids)
{
    int idx = blockIdx.x * blockDim.x + threadIdx.x;
    if (idx >= BB*NHH*SS*(HDD/2)) return;
    const int i  = idx & 31;
    const int s  = (idx >> 5) & (SS - 1);
    const int bh = idx >> 16;
    const int b  = bh >> 4;

    int p = pos_ids[b*SS + s];
    p = min(max(p, 0), SS - 1);

    const float inv = expf(-(float)(2*i) / (float)HDD * logf(10000.0f));
    const float ang = (float)p * inv;
    float sn, cs;
    sincosf(ang, &sn, &cs);

    const int base = (bh*SS + s)*HDD;
    float q0 = Q[base + i], q1 = Q[base + i + 32];
    Q[base + i]      = q0*cs - q1*sn;
    Q[base + i + 32] = q1*cs + q0*sn;
    float k0 = K[base + i], k1 = K[base + i + 32];
    K[base + i]      = k0*cs - k1*sn;
    K[base + i + 32] = k1*cs + k0*sn;
}

// ---------------- tensor-core flash attention (causal, tf32 MMA) ------------
// Q tile 128 x K tile 64. 256 threads = 8 warps; warp w owns rows 16w..16w+15.
// Smem strides: Q/K/P = 68 (row-indexed fragment loads conflict-free),
// V = 72 (transposed B-operand loads conflict-free).
#define FQ 128
#define FK 64
#define QSTR 68
#define KSTR 68
#define PSTR 68
#define VSTR 72

__global__ void __launch_bounds__(256) flash_tc(const float* __restrict__ Q,
                                                const float* __restrict__ K,
                                                const float* __restrict__ V,
                                                float* __restrict__ AO)
{
    extern __shared__ uint32_t fsm[];
    uint32_t* Qs = fsm;                       // 128*68
    uint32_t* Ks = Qs + FQ*QSTR;              // 64*68
    uint32_t* Vs = Ks + FK*KSTR;              // 64*72
    uint32_t* Ps = Vs + FK*VSTR;              // 128*68

    const int tid  = threadIdx.x;
    const int w    = tid >> 5;
    const int lane = tid & 31;
    const int g    = lane >> 2;
    const int tg   = lane & 3;
    const int bh   = blockIdx.y;
    const int qt   = (int)(gridDim.x - 1) - (int)blockIdx.x;  // heavy tiles first
    const int q0   = qt * FQ;
    const size_t base = (size_t)bh * SS * HDD;

    // load Q tile (pre-scaled by 1/sqrt(HD)=0.125), tf32
    for (int t = tid; t < FQ*16; t += 256) {
        const int r = t >> 4, c4 = (t & 15) * 4;
        float4 v = *(const float4*)&Q[base + (size_t)(q0 + r)*HDD + c4];
        uint4 u = make_uint4(f2tf32(v.x*0.125f), f2tf32(v.y*0.125f),
                             f2tf32(v.z*0.125f), f2tf32(v.w*0.125f));
        *(uint4*)&Qs[r*QSTR + c4] = u;
    }

    float m0r = -1e30f, m1r = -1e30f, l0 = 0.f, l1 = 0.f;
    float acc[8][4];
    #pragma unroll
    for (int ni = 0; ni < 8; ni++)
        #pragma unroll
        for (int r = 0; r < 4; r++) acc[ni][r] = 0.f;

    const int rloc0 = w*16 + g;          // local row of c0/c1
    const int row0  = q0 + rloc0;        // global
    const int row1  = row0 + 8;

    const int ktiles = 2*qt + 2;
    for (int kt = 0; kt < ktiles; kt++) {
        const int k0 = kt * FK;
        __syncthreads();
        for (int t = tid; t < FK*16; t += 256) {
            const int r = t >> 4, c4 = (t & 15) * 4;
            float4 kv = *(const float4*)&K[base + (size_t)(k0 + r)*HDD + c4];
            *(uint4*)&Ks[r*KSTR + c4] = make_uint4(f2tf32(kv.x), f2tf32(kv.y),
                                                   f2tf32(kv.z), f2tf32(kv.w));
            float4 vv = *(const float4*)&V[base + (size_t)(k0 + r)*HDD + c4];
            *(uint4*)&Vs[r*VSTR + c4] = make_uint4(f2tf32(vv.x), f2tf32(vv.y),
                                                   f2tf32(vv.z), f2tf32(vv.w));
        }
        __syncthreads();

        // GEMM1: scores(16x64 per warp) = Q_strip . K^T
        float sc[8][4];
        #pragma unroll
        for (int ni = 0; ni < 8; ni++)
            #pragma unroll
            for (int r = 0; r < 4; r++) sc[ni][r] = 0.f;

        #pragma unroll
        for (int kk = 0; kk < 8; kk++) {
            const int kc = kk * 8;
            uint32_t a[4];
            const int rb = rloc0*QSTR + kc + tg;
            a[0] = Qs[rb];
            a[1] = Qs[rb + 8*QSTR];
            a[2] = Qs[rb + 4];
            a[3] = Qs[rb + 8*QSTR + 4];
            #pragma unroll
            for (int ni = 0; ni < 8; ni++) {
                uint32_t b[2];
                const int nb = (ni*8 + g)*KSTR + kc + tg;
                b[0] = Ks[nb];
                b[1] = Ks[nb + 4];
                mma_tf32(sc[ni], a, b);
            }
        }

        // causal mask on diagonal tiles
        if (kt >= 2*qt) {
            #pragma unroll
            for (int ni = 0; ni < 8; ni++) {
                const int c = k0 + ni*8 + 2*tg;
                if (c     > row0) sc[ni][0] = -1e30f;
                if (c + 1 > row0) sc[ni][1] = -1e30f;
                if (c     > row1) sc[ni][2] = -1e30f;
                if (c + 1 > row1) sc[ni][3] = -1e30f;
            }
        }

        // online softmax (rows row0, row1; reduce within quad)
        float mx0 = -1e30f, mx1 = -1e30f;
        #pragma unroll
        for (int ni = 0; ni < 8; ni++) {
            mx0 = fmaxf(mx0, fmaxf(sc[ni][0], sc[ni][1]));
            mx1 = fmaxf(mx1, fmaxf(sc[ni][2], sc[ni][3]));
        }
        #pragma unroll
        for (int off = 1; off < 4; off <<= 1) {
            mx0 = fmaxf(mx0, __shfl_xor_sync(0xffffffffu, mx0, off));
            mx1 = fmaxf(mx1, __shfl_xor_sync(0xffffffffu, mx1, off));
        }
        const float mn0 = fmaxf(m0r, mx0);
        const float mn1 = fmaxf(m1r, mx1);
        const float al0 = __expf(m0r - mn0);
        const float al1 = __expf(m1r - mn1);

        float s0 = 0.f, s1 = 0.f;
        #pragma unroll
        for (int ni = 0; ni < 8; ni++) {
            sc[ni][0] = __expf(sc[ni][0] - mn0);
            sc[ni][1] = __expf(sc[ni][1] - mn0);
            sc[ni][2] = __expf(sc[ni][2] - mn1);
            sc[ni][3] = __expf(sc[ni][3] - mn1);
            s0 += sc[ni][0] + sc[ni][1];
            s1 += sc[ni][2] + sc[ni][3];
        }
        #pragma unroll
        for (int off = 1; off < 4; off <<= 1) {
            s0 += __shfl_xor_sync(0xffffffffu, s0, off);
            s1 += __shfl_xor_sync(0xffffffffu, s1, off);
        }
        l0 = l0*al0 + s0;
        l1 = l1*al1 + s1;
        m0r = mn0; m1r = mn1;

        #pragma unroll
        for (int ni = 0; ni < 8; ni++) {
            acc[ni][0] *= al0; acc[ni][1] *= al0;
            acc[ni][2] *= al1; acc[ni][3] *= al1;
            // store P strip (tf32) — warp-private rows
            const int col = ni*8 + 2*tg;
            *(uint2*)&Ps[rloc0*PSTR + col] =
                make_uint2(f2tf32(sc[ni][0]), f2tf32(sc[ni][1]));
            *(uint2*)&Ps[(rloc0 + 8)*PSTR + col] =
                make_uint2(f2tf32(sc[ni][2]), f2tf32(sc[ni][3]));
        }
        __syncwarp();

        // GEMM2: acc += P_strip . V
        #pragma unroll
        for (int kk = 0; kk < 8; kk++) {
            const int kc = kk * 8;
            uint32_t a[4];
            const int pb = rloc0*PSTR + kc + tg;
            a[0] = Ps[pb];
            a[1] = Ps[pb + 8*PSTR];
            a[2] = Ps[pb + 4];
            a[3] = Ps[pb + 8*PSTR + 4];
            #pragma unroll
            for (int ni = 0; ni < 8; ni++) {
                uint32_t b[2];
                b[0] = Vs[(kc + tg    )*VSTR + ni*8 + g];
                b[1] = Vs[(kc + tg + 4)*VSTR + ni*8 + g];
                mma_tf32(acc[ni], a, b);
            }
        }
    }

    // epilogue
    const float il0 = 1.f / l0;
    const float il1 = 1.f / l1;
    const int b_ = bh >> 4, nh = bh & 15;
    #pragma unroll
    for (int ni = 0; ni < 8; ni++) {
        const int col = nh*HDD + ni*8 + 2*tg;
        *(float2*)&AO[(size_t)(b_*SS + row0)*HH + col] =
            make_float2(acc[ni][0]*il0, acc[ni][1]*il0);
        *(float2*)&AO[(size_t)(b_*SS + row1)*HH + col] =
            make_float2(acc[ni][2]*il1, acc[ni][3]*il1);
    }
}

// ---------------- launcher ---------------------------------------------------
static const int GEMM_SMEM  = 2 * 8192 * (int)sizeof(uint32_t);                 // 65536
static const int FLASH_SMEM = (FQ*QSTR + FK*KSTR + FK*VSTR + FQ*PSTR) * 4;      // 105472

extern "C" void kernel_launch(void* const* d_in, const int* in_sizes, int n_in,
                              void* d_out, int out_size)
{
    (void)in_sizes; (void)n_in; (void)out_size;
    const float* hs = (const float*)d_in[0];
    const float* wq = (const float*)d_in[2];
    const float* wk = (const float*)d_in[3];
    const float* wv = (const float*)d_in[4];
    const float* wo = (const float*)d_in[5];
    const int*  pos = (const int*)d_in[6];
    float* out = (float*)d_out;

    float *Q, *K, *V, *AO;
    cudaGetSymbolAddress((void**)&Q,  g_Q);
    cudaGetSymbolAddress((void**)&K,  g_K);
    cudaGetSymbolAddress((void**)&V,  g_V);
    cudaGetSymbolAddress((void**)&AO, g_AO);

    static bool attr_done = false;
    if (!attr_done) {
        cudaFuncSetAttribute(gemm_tf32<0>,
                             cudaFuncAttributeMaxDynamicSharedMemorySize, GEMM_SMEM);
        cudaFuncSetAttribute(gemm_tf32<1>,
                             cudaFuncAttributeMaxDynamicSharedMemorySize, GEMM_SMEM);
        cudaFuncSetAttribute(flash_tc,
                             cudaFuncAttributeMaxDynamicSharedMemorySize, FLASH_SMEM);
        attr_done = true;
    }

    const dim3 gemm_grid(HH/128, MM/128);   // (8, 32)
    gemm_tf32<0><<<gemm_grid, 256, GEMM_SMEM>>>(hs, wq, Q);
    gemm_tf32<0><<<gemm_grid, 256, GEMM_SMEM>>>(hs, wk, K);
    gemm_tf32<0><<<gemm_grid, 256, GEMM_SMEM>>>(hs, wv, V);

    rope_kernel<<<(BB*NHH*SS*(HDD/2)) / 256, 256>>>(Q, K, pos);

    flash_tc<<<dim3(SS/FQ, BB*NHH), 256, FLASH_SMEM>>>(Q, K, V, AO);

    gemm_tf32<1><<<gemm_grid, 256, GEMM_SMEM>>>(AO, wo, out);
}